// round 13
// baseline (speedup 1.0000x reference)
#include <cuda_runtime.h>
#include <math.h>

#define NIMG 48            // B*C = 16*3
#define NBATCH 16
#define N 1024
#define OUT_HW 224
#define W 513              // kept kx columns (Hermitian half)
#define WB 514             // padded kx rows in g_B
#define KRAD (1024.0f/224.0f)
#define KSCL (224.0f/1024.0f)

// padded shared indexing (generic form, used only in the Hermitian unpack)
#define P(i)  ((i) + ((i) >> 4) + ((i) >> 8))
#define S_SZ  1092
#define TW_SZ 272

typedef unsigned long long u64;

// scratch (static device arrays; no allocation allowed)
__device__ u64   g_B[(size_t)NIMG * WB * N];        // column-major spectra [img][kx][y]
__device__ float g_T[(size_t)NIMG * N * OUT_HW];    // ky-resized [img][kxs][oy]
__device__ u64   g_tw[256];
__device__ unsigned int g_mn[NBATCH];
__device__ unsigned int g_mx[NBATCH];

// ---------- packed f32x2 complex primitives ----------
__device__ __forceinline__ u64 pk(float x, float y) {
    u64 r; asm("mov.b64 %0, {%1,%2};" : "=l"(r) : "f"(x), "f"(y)); return r;
}
__device__ __forceinline__ void upk(u64 a, float& x, float& y) {
    asm("mov.b64 {%0,%1}, %2;" : "=f"(x), "=f"(y) : "l"(a));
}
__device__ __forceinline__ u64 vadd(u64 a, u64 b) {
    u64 r; asm("add.rn.f32x2 %0, %1, %2;" : "=l"(r) : "l"(a), "l"(b)); return r;
}
__device__ __forceinline__ u64 vfma(u64 a, u64 b, u64 c) {
    u64 r; asm("fma.rn.f32x2 %0, %1, %2, %3;" : "=l"(r) : "l"(a), "l"(b), "l"(c)); return r;
}
#define K_NEG1 0xBF800000BF800000ULL   // (-1,-1)
#define K_PM1  0xBF8000003F800000ULL   // lo:+1, hi:-1
#define K_MP1  0x3F800000BF800000ULL   // lo:-1, hi:+1
__device__ __forceinline__ u64 vsub(u64 a, u64 b) { return vfma(b, K_NEG1, a); }  // a-b

// scalar complex multiply on packed values
__device__ __forceinline__ u64 cmul(u64 a, u64 b) {
    float ax, ay, bx, by; upk(a, ax, ay); upk(b, bx, by);
    return pk(ax*bx - ay*by, ax*by + ay*bx);
}
__device__ __forceinline__ u64 cmulc(u64 a, float bx, float by) {
    float ax, ay; upk(a, ax, ay);
    return pk(ax*bx - ay*by, ax*by + ay*bx);
}

// packed radix-4 DIT butterfly, in place
__device__ __forceinline__ void bfly4p(u64& x0, u64& x1, u64& x2, u64& x3) {
    u64 u0 = vadd(x0, x2);
    u64 u1 = vsub(x0, x2);
    u64 u2 = vadd(x1, x3);
    u64 u3 = vsub(x1, x3);
    x0 = vadd(u0, u2);
    x2 = vsub(u0, u2);
    float ux, uy; upk(u3, ux, uy);
    u64 sw = pk(uy, ux);
    x1 = vfma(sw, K_PM1, u1);   // (u1.x + u3.y, u1.y - u3.x)
    x3 = vfma(sw, K_MP1, u1);   // (u1.x - u3.y, u1.y + u3.x)
}

// butterfly with precomputed twiddle powers
__device__ __forceinline__ void stage3(u64& a0, u64& a1, u64& a2, u64& a3,
                                       u64 w1, u64 w2, u64 w3) {
    a1 = cmul(a1, w1); a2 = cmul(a2, w2); a3 = cmul(a3, w3);
    bfly4p(a0, a1, a2, a3);
}

// base-4 digit reversal of a 6-bit index (64 = 4^3), self-inverse
__device__ __forceinline__ int rev4_6(int b) {
    return ((b & 3) << 4) | (b & 12) | (b >> 4);
}

// ---------- FFT phases (1024 pts, 64 threads/FFT, 16 pts/thread) ----------
// phase 1: stages 0+1 in registers, store to shared at affine offsets.
// Caller passes b = rev4_6(L) so the global loads stay contiguous in L.
__device__ __forceinline__ void fft_ph1(u64 x[16], u64* s, int b) {
    #pragma unroll
    for (int k = 0; k < 4; ++k) bfly4p(x[4*k], x[4*k+1], x[4*k+2], x[4*k+3]);
    bfly4p(x[0], x[4], x[8], x[12]);                       // pos=0: no twiddle
    x[5]  = cmulc(x[5],   0.92387953f, -0.38268343f);      // pos=1: w, w^2, w^3
    x[9]  = cmulc(x[9],   0.70710678f, -0.70710678f);
    x[13] = cmulc(x[13],  0.38268343f, -0.92387953f);
    bfly4p(x[1], x[5], x[9], x[13]);
    x[6]  = cmulc(x[6],   0.70710678f, -0.70710678f);      // pos=2
    x[10] = cmulc(x[10],  0.0f,        -1.0f);
    x[14] = cmulc(x[14], -0.70710678f, -0.70710678f);
    bfly4p(x[2], x[6], x[10], x[14]);
    x[7]  = cmulc(x[7],   0.38268343f, -0.92387953f);      // pos=3
    x[11] = cmulc(x[11], -0.70710678f, -0.70710678f);
    x[15] = cmulc(x[15], -0.92387953f,  0.38268343f);
    bfly4p(x[3], x[7], x[11], x[15]);
    int b17 = 17*b + (b >> 4);          // == P(16b + j) - j
    #pragma unroll
    for (int j = 0; j < 16; ++j) s[b17 + j] = x[j];
}

// phase 2: stages 2+3 in registers. P(c+16q2+64q3+256hi) = (c+273hi)+17q2+68q3
__device__ __forceinline__ void fft_ph2(u64* s, const u64* tw, int L) {
    int c = L & 15, hi = L >> 4;
    int base = c + 273*hi;
    u64 x[16];
    #pragma unroll
    for (int q3 = 0; q3 < 4; ++q3)
        #pragma unroll
        for (int q2 = 0; q2 < 4; ++q2)
            x[q2 + 4*q3] = s[base + 17*q2 + 68*q3];
    u64 w1 = tw[17*c];                  // PT(16c) = 17c
    u64 w2 = cmul(w1, w1);
    u64 w3 = cmul(w2, w1);
    #pragma unroll
    for (int q3 = 0; q3 < 4; ++q3)
        stage3(x[4*q3], x[4*q3+1], x[4*q3+2], x[4*q3+3], w1, w2, w3);
    u64 v1 = tw[4*c + (c >> 2)];        // PT(4c)
    const float wc[4] = {1.0f, 0.92387953f, 0.70710678f, 0.38268343f};
    const float ws[4] = {0.0f, -0.38268343f, -0.70710678f, -0.92387953f};
    #pragma unroll
    for (int q2 = 0; q2 < 4; ++q2) {
        u64 w = (q2 == 0) ? v1 : cmulc(v1, wc[q2], ws[q2]);
        u64 ww2 = cmul(w, w);
        u64 ww3 = cmul(ww2, w);
        stage3(x[q2], x[q2+4], x[q2+8], x[q2+12], w, ww2, ww3);
    }
    #pragma unroll
    for (int q3 = 0; q3 < 4; ++q3)
        #pragma unroll
        for (int q2 = 0; q2 < 4; ++q2)
            s[base + 17*q2 + 68*q3] = x[q2 + 4*q3];
}

// phase 3: stage 4. P(4L+k+256q) = (4L+(L>>2)) + k + 273q; tw index = base+k.
// Result: x[k+4q] = DFT[4L+k+256q] (natural order).
__device__ __forceinline__ void fft_ph3(u64* s, const u64* tw, int L, u64 x[16]) {
    int base = 4*L + (L >> 2);
    #pragma unroll
    for (int k = 0; k < 4; ++k) {
        u64 w1 = tw[base + k];
        u64 w2 = cmul(w1, w1);
        u64 w3 = cmul(w2, w1);
        u64 a0 = s[base + k];
        u64 a1 = s[base + k + 273];
        u64 a2 = s[base + k + 546];
        u64 a3 = s[base + k + 819];
        a1 = cmul(a1, w1); a2 = cmul(a2, w2); a3 = cmul(a3, w3);
        bfly4p(a0, a1, a2, a3);
        x[k] = a0; x[k+4] = a1; x[k+8] = a2; x[k+12] = a3;
    }
}

__global__ void k_init(void) {
    int t = threadIdx.x;
    if (t < NBATCH) { g_mn[t] = 0x7f800000u; g_mx[t] = 0u; }
    float sn, cs;
    sincosf(-6.283185307179586f * (float)t / 1024.0f, &sn, &cs);
    g_tw[t] = pk(cs, sn);
}

// 4 FFTs per 256-thread block; each FFT = two real rows (ya, ya+512) packed.
// Hermitian unpack writes transposed 32B chunks directly into g_B.
__global__ void __launch_bounds__(256) k_rowfft(const float* __restrict__ in) {
    __shared__ u64 s[4][S_SZ];
    __shared__ u64 tw[TW_SZ];
    int T = threadIdx.x, f = T >> 6, L = T & 63;
    tw[T + (T >> 4)] = g_tw[T];         // PT(T)
    int bx  = blockIdx.x;               // img*128 + rg
    int img = bx >> 7;
    int rg  = bx & 127;
    int ya  = 4*rg + f;
    __syncthreads();                    // tw ready

    const float* ra = in + ((size_t)img * N + ya) * N;
    const float* rb = ra + (size_t)512 * N;
    // relabeled: this thread runs butterfly group rev4_6(L) -> contiguous loads
    u64 x[16];
    #pragma unroll
    for (int j = 0; j < 16; ++j) {
        int gi = L + 64*((j >> 2) & 3) + 256*(j & 3);
        x[j] = pk(ra[gi], rb[gi]);
    }
    fft_ph1(x, s[f], rev4_6(L));
    __syncthreads();
    fft_ph2(s[f], tw, L);
    __syncthreads();
    fft_ph3(s[f], tw, L, x);
    {   // store naturally-ordered results (same addresses ph3 read: no sync needed)
        int base = 4*L + (L >> 2);
        #pragma unroll
        for (int k = 0; k < 4; ++k)
            #pragma unroll
            for (int q = 0; q < 4; ++q)
                s[f][base + k + 273*q] = x[k + 4*q];
    }
    __syncthreads();                    // all 4 FFTs resident

    // transposed Hermitian unpack: keep kx = 0..512
    int ybase = 4 * rg;
    for (int e = T; e < W; e += 256) {
        int em = (N - e) & (N - 1);
        u64 va[4], vb[4];
        #pragma unroll
        for (int g = 0; g < 4; ++g) {
            float zx, zy, mxx, mxy;
            upk(s[g][P(e)],  zx, zy);
            upk(s[g][P(em)], mxx, mxy);
            va[g] = pk(0.5f*(zx + mxx), 0.5f*(zy - mxy));
            vb[g] = pk(0.5f*(zy + mxy), 0.5f*(mxx - zx));
        }
        u64* pa = g_B + ((size_t)img * WB + e) * N + ybase;
        u64* pb = pa + 512;
        *reinterpret_cast<ulonglong2*>(pa)     = make_ulonglong2(va[0], va[1]);
        *reinterpret_cast<ulonglong2*>(pa + 2) = make_ulonglong2(va[2], va[3]);
        *reinterpret_cast<ulonglong2*>(pb)     = make_ulonglong2(vb[0], vb[1]);
        *reinterpret_cast<ulonglong2*>(pb + 2) = make_ulonglong2(vb[2], vb[3]);
    }
}

// One FFT = one kept column kx. 2 columns per 128-thread block.
// m aliases the exchange buffer (results live in registers after ph3).
__global__ void __launch_bounds__(128) k_colfft(void) {
    __shared__ u64 s[2][S_SZ];
    __shared__ u64 tw[TW_SZ];
    __shared__ float red[8];            // 4 warps: min[0..3], max[4..7]
    int T = threadIdx.x, f = T >> 6, L = T & 63;
    #pragma unroll
    for (int j = T; j < 256; j += 128) tw[j + (j >> 4)] = g_tw[j];
    int bx  = blockIdx.x;               // img*257 + cg
    int img = bx / 257;
    int cg  = bx - img * 257;
    int kx  = 2*cg + f;                 // 0..513 (513 is padding)
    bool valid = (kx < W);
    __syncthreads();                    // tw ready

    const u64* cp = g_B + ((size_t)img * WB + kx) * N;
    // relabeled: contiguous 256B/warp loads
    u64 x[16];
    #pragma unroll
    for (int j = 0; j < 16; ++j)
        x[j] = cp[L + 64*((j >> 2) & 3) + 256*(j & 3)];
    fft_ph1(x, s[f], rev4_6(L));
    __syncthreads();
    fft_ph2(s[f], tw, L);
    __syncthreads();
    fft_ph3(s[f], tw, L, x);
    __syncthreads();                    // all ph3 reads of s done: safe to alias

    // log-magnitude straight from registers; fftshift along ky.
    // m overlays s[f] (4096B of 8736B available).
    float* m = reinterpret_cast<float*>(s[f]);
    float mn = 3.4e38f, mx = 0.0f;
    int mbase = 4*L;
    #pragma unroll
    for (int k = 0; k < 4; ++k)
        #pragma unroll
        for (int q = 0; q < 4; ++q) {
            int cshift = (256*q + 512) & (N - 1);   // literal per q: 512,768,0,256
            float vx, vy; upk(x[k + 4*q], vx, vy);
            float mag = log1pf(sqrtf(vx*vx + vy*vy));
            m[mbase + k + cshift] = mag;
            mn = fminf(mn, mag); mx = fmaxf(mx, mag);
        }
    #pragma unroll
    for (int o = 16; o; o >>= 1) {
        mn = fminf(mn, __shfl_xor_sync(0xffffffffu, mn, o));
        mx = fmaxf(mx, __shfl_xor_sync(0xffffffffu, mx, o));
    }
    int wid = T >> 5;
    if ((T & 31) == 0) { red[wid] = mn; red[4 + wid] = mx; }
    __syncthreads();                    // red + m[] ready
    if (L == 0 && valid) {
        float a  = fminf(red[2*f], red[2*f + 1]);
        float c2 = fmaxf(red[4 + 2*f], red[4 + 2*f + 1]);
        int b = img / 3;
        atomicMin(&g_mn[b], __float_as_uint(a));
        atomicMax(&g_mx[b], __float_as_uint(c2));
    }

    // antialiased triangle resize along kys (ramp weights), column + mirror
    if (valid) {
        int kxs1 = (kx + 512) & (N - 1);
        int kxs2 = 512 - kx;
        float* gt1 = g_T + ((size_t)img * N + kxs1) * OUT_HW;
        float* gt2 = g_T + ((size_t)img * N + kxs2) * OUT_HW;
        for (int oy = L; oy < OUT_HW; oy += 64) {
            float sf = ((float)oy + 0.5f) * (1024.0f/224.0f) - 0.5f;
            int i0 = max(0, (int)ceilf(sf - KRAD));
            int i1 = min(N - 1, (int)floorf(sf + KRAD));
            int ip = (int)floorf(sf);
            float acc1 = 0.0f, acc2 = 0.0f, sw = 0.0f;
            float w = 1.0f - (sf - (float)i0) * KSCL;
            int i = i0;
            for (; i <= ip; ++i) {
                acc1 += w * m[i];
                acc2 += w * m[(N - i) & (N - 1)];
                sw += w; w += KSCL;
            }
            w = 1.0f - ((float)i - sf) * KSCL;
            for (; i <= i1; ++i) {
                acc1 += w * m[i];
                acc2 += w * m[(N - i) & (N - 1)];
                sw += w; w -= KSCL;
            }
            float inv = 1.0f / sw;
            gt1[oy] = acc1 * inv;
            gt2[oy] = acc2 * inv;
        }
    }
}

// kx-resize + normalization. Block = (img, 8-oy tile): stages the g_T slice
// [1024 kxs][8 oy] into shared (each element read exactly once, coalesced),
// thread = ox with tap weights/offsets hoisted across the 8 oy, stores
// contiguous 896B rows.
__global__ void __launch_bounds__(224) k_resize2(float* __restrict__ out) {
    __shared__ float ms[N * 9];         // [kxs][8 oy], pad 9 floats/row
    int bx  = blockIdx.x;               // img*28 + ot
    int img = bx / 28;
    int ot  = bx - img * 28;
    int oy0 = ot * 8;
    int T   = threadIdx.x;              // = ox

    const float* gt = g_T + (size_t)img * N * OUT_HW + oy0;
    for (int e = T; e < N * 8; e += 224) {
        int kxs = e >> 3, o = e & 7;
        ms[kxs * 9 + o] = gt[kxs * OUT_HW + o];
    }
    __syncthreads();

    float sf = ((float)T + 0.5f) * (1024.0f/224.0f) - 0.5f;
    int i0 = max(0, (int)ceilf(sf - KRAD));
    // precompute (clamped) shared offsets + weights; out-of-range taps get w=0
    int   off[11];
    float wt[11];
    float sw = 0.0f;
    #pragma unroll
    for (int j = 0; j < 11; ++j) {
        int i = i0 + j;
        float wv = fmaxf(0.0f, 1.0f - fabsf(sf - (float)i) * KSCL);
        if (i > N - 1) wv = 0.0f;       // exclude taps beyond the grid (edge renorm)
        wt[j]  = wv;
        sw    += wv;
        off[j] = min(i, N - 1) * 9;
    }
    float inv = 1.0f / sw;
    int b = img / 3;
    float mn  = __uint_as_float(g_mn[b]);
    float mxv = __uint_as_float(g_mx[b]);
    float nrm = 1.0f / (mxv - mn + 1e-8f);

    float* op = out + ((size_t)img * OUT_HW + oy0) * OUT_HW + T;
    #pragma unroll
    for (int o = 0; o < 8; ++o) {
        float acc = 0.0f;
        #pragma unroll
        for (int j = 0; j < 11; ++j)
            acc += wt[j] * ms[off[j] + o];
        op[o * OUT_HW] = (acc * inv - mn) * nrm;
    }
}

extern "C" void kernel_launch(void* const* d_in, const int* in_sizes, int n_in,
                              void* d_out, int out_size) {
    (void)in_sizes; (void)n_in; (void)out_size;
    const float* in = (const float*)d_in[0];
    float* out = (float*)d_out;

    k_init<<<1, 256>>>();
    k_rowfft<<<NIMG * 128, 256>>>(in);
    k_colfft<<<NIMG * 257, 128>>>();
    k_resize2<<<NIMG * 28, 224>>>(out);
}

// round 14
// speedup vs baseline: 1.0718x; 1.0718x over previous
#include <cuda_runtime.h>
#include <math.h>

#define NIMG 48            // B*C = 16*3
#define NBATCH 16
#define N 1024
#define OUT_HW 224
#define W 513              // kept kx columns (Hermitian half)
#define WB 514             // padded kx rows in g_B
#define KRAD (1024.0f/224.0f)
#define KSCL (224.0f/1024.0f)

// padded shared indexing (generic form, used only in the Hermitian unpack)
#define P(i)  ((i) + ((i) >> 4) + ((i) >> 8))
#define S_SZ  1092
#define TW_SZ 272

typedef unsigned long long u64;

// scratch (static device arrays; no allocation allowed)
__device__ u64   g_B[(size_t)NIMG * WB * N];        // column-major spectra [img][kx][y]
__device__ float g_T[(size_t)NIMG * N * OUT_HW];    // ky-resized [img][kxs][oy]
__device__ u64   g_tw[256];
__device__ unsigned int g_mn[NBATCH];
__device__ unsigned int g_mx[NBATCH];

// ---------- packed f32x2 complex primitives ----------
__device__ __forceinline__ u64 pk(float x, float y) {
    u64 r; asm("mov.b64 %0, {%1,%2};" : "=l"(r) : "f"(x), "f"(y)); return r;
}
__device__ __forceinline__ void upk(u64 a, float& x, float& y) {
    asm("mov.b64 {%0,%1}, %2;" : "=f"(x), "=f"(y) : "l"(a));
}
__device__ __forceinline__ u64 vadd(u64 a, u64 b) {
    u64 r; asm("add.rn.f32x2 %0, %1, %2;" : "=l"(r) : "l"(a), "l"(b)); return r;
}
__device__ __forceinline__ u64 vfma(u64 a, u64 b, u64 c) {
    u64 r; asm("fma.rn.f32x2 %0, %1, %2, %3;" : "=l"(r) : "l"(a), "l"(b), "l"(c)); return r;
}
#define K_NEG1 0xBF800000BF800000ULL   // (-1,-1)
#define K_PM1  0xBF8000003F800000ULL   // lo:+1, hi:-1
#define K_MP1  0x3F800000BF800000ULL   // lo:-1, hi:+1
__device__ __forceinline__ u64 vsub(u64 a, u64 b) { return vfma(b, K_NEG1, a); }  // a-b

// scalar complex multiply on packed values
__device__ __forceinline__ u64 cmul(u64 a, u64 b) {
    float ax, ay, bx, by; upk(a, ax, ay); upk(b, bx, by);
    return pk(ax*bx - ay*by, ax*by + ay*bx);
}
__device__ __forceinline__ u64 cmulc(u64 a, float bx, float by) {
    float ax, ay; upk(a, ax, ay);
    return pk(ax*bx - ay*by, ax*by + ay*bx);
}

// packed radix-4 DIT butterfly, in place
__device__ __forceinline__ void bfly4p(u64& x0, u64& x1, u64& x2, u64& x3) {
    u64 u0 = vadd(x0, x2);
    u64 u1 = vsub(x0, x2);
    u64 u2 = vadd(x1, x3);
    u64 u3 = vsub(x1, x3);
    x0 = vadd(u0, u2);
    x2 = vsub(u0, u2);
    float ux, uy; upk(u3, ux, uy);
    u64 sw = pk(uy, ux);
    x1 = vfma(sw, K_PM1, u1);   // (u1.x + u3.y, u1.y - u3.x)
    x3 = vfma(sw, K_MP1, u1);   // (u1.x - u3.y, u1.y + u3.x)
}

// butterfly with precomputed twiddle powers
__device__ __forceinline__ void stage3(u64& a0, u64& a1, u64& a2, u64& a3,
                                       u64 w1, u64 w2, u64 w3) {
    a1 = cmul(a1, w1); a2 = cmul(a2, w2); a3 = cmul(a3, w3);
    bfly4p(a0, a1, a2, a3);
}

// base-4 digit reversal of a 6-bit index (64 = 4^3), self-inverse
__device__ __forceinline__ int rev4_6(int b) {
    return ((b & 3) << 4) | (b & 12) | (b >> 4);
}

// ---------- FFT phases (1024 pts, 64 threads/FFT, 16 pts/thread) ----------
// phase 1: stages 0+1 in registers, store to shared at affine offsets.
// Caller passes b = rev4_6(L) so the global loads stay contiguous in L.
__device__ __forceinline__ void fft_ph1(u64 x[16], u64* s, int b) {
    #pragma unroll
    for (int k = 0; k < 4; ++k) bfly4p(x[4*k], x[4*k+1], x[4*k+2], x[4*k+3]);
    bfly4p(x[0], x[4], x[8], x[12]);                       // pos=0: no twiddle
    x[5]  = cmulc(x[5],   0.92387953f, -0.38268343f);      // pos=1: w, w^2, w^3
    x[9]  = cmulc(x[9],   0.70710678f, -0.70710678f);
    x[13] = cmulc(x[13],  0.38268343f, -0.92387953f);
    bfly4p(x[1], x[5], x[9], x[13]);
    x[6]  = cmulc(x[6],   0.70710678f, -0.70710678f);      // pos=2
    x[10] = cmulc(x[10],  0.0f,        -1.0f);
    x[14] = cmulc(x[14], -0.70710678f, -0.70710678f);
    bfly4p(x[2], x[6], x[10], x[14]);
    x[7]  = cmulc(x[7],   0.38268343f, -0.92387953f);      // pos=3
    x[11] = cmulc(x[11], -0.70710678f, -0.70710678f);
    x[15] = cmulc(x[15], -0.92387953f,  0.38268343f);
    bfly4p(x[3], x[7], x[11], x[15]);
    int b17 = 17*b + (b >> 4);          // == P(16b + j) - j
    #pragma unroll
    for (int j = 0; j < 16; ++j) s[b17 + j] = x[j];
}

// phase 2: stages 2+3 in registers. P(c+16q2+64q3+256hi) = (c+273hi)+17q2+68q3
__device__ __forceinline__ void fft_ph2(u64* s, const u64* tw, int L) {
    int c = L & 15, hi = L >> 4;
    int base = c + 273*hi;
    u64 x[16];
    #pragma unroll
    for (int q3 = 0; q3 < 4; ++q3)
        #pragma unroll
        for (int q2 = 0; q2 < 4; ++q2)
            x[q2 + 4*q3] = s[base + 17*q2 + 68*q3];
    u64 w1 = tw[17*c];                  // PT(16c) = 17c
    u64 w2 = cmul(w1, w1);
    u64 w3 = cmul(w2, w1);
    #pragma unroll
    for (int q3 = 0; q3 < 4; ++q3)
        stage3(x[4*q3], x[4*q3+1], x[4*q3+2], x[4*q3+3], w1, w2, w3);
    u64 v1 = tw[4*c + (c >> 2)];        // PT(4c)
    const float wc[4] = {1.0f, 0.92387953f, 0.70710678f, 0.38268343f};
    const float ws[4] = {0.0f, -0.38268343f, -0.70710678f, -0.92387953f};
    #pragma unroll
    for (int q2 = 0; q2 < 4; ++q2) {
        u64 w = (q2 == 0) ? v1 : cmulc(v1, wc[q2], ws[q2]);
        u64 ww2 = cmul(w, w);
        u64 ww3 = cmul(ww2, w);
        stage3(x[q2], x[q2+4], x[q2+8], x[q2+12], w, ww2, ww3);
    }
    #pragma unroll
    for (int q3 = 0; q3 < 4; ++q3)
        #pragma unroll
        for (int q2 = 0; q2 < 4; ++q2)
            s[base + 17*q2 + 68*q3] = x[q2 + 4*q3];
}

// phase 3: stage 4. P(4L+k+256q) = (4L+(L>>2)) + k + 273q; tw index = base+k.
// Result: x[k+4q] = DFT[4L+k+256q] (natural order).
__device__ __forceinline__ void fft_ph3(u64* s, const u64* tw, int L, u64 x[16]) {
    int base = 4*L + (L >> 2);
    #pragma unroll
    for (int k = 0; k < 4; ++k) {
        u64 w1 = tw[base + k];
        u64 w2 = cmul(w1, w1);
        u64 w3 = cmul(w2, w1);
        u64 a0 = s[base + k];
        u64 a1 = s[base + k + 273];
        u64 a2 = s[base + k + 546];
        u64 a3 = s[base + k + 819];
        a1 = cmul(a1, w1); a2 = cmul(a2, w2); a3 = cmul(a3, w3);
        bfly4p(a0, a1, a2, a3);
        x[k] = a0; x[k+4] = a1; x[k+8] = a2; x[k+12] = a3;
    }
}

__global__ void k_init(void) {
    int t = threadIdx.x;
    if (t < NBATCH) { g_mn[t] = 0x7f800000u; g_mx[t] = 0u; }
    float sn, cs;
    sincosf(-6.283185307179586f * (float)t / 1024.0f, &sn, &cs);
    g_tw[t] = pk(cs, sn);
}

// 4 FFTs per 256-thread block; each FFT = two real rows (ya, ya+512) packed.
// Hermitian unpack writes transposed 32B chunks directly into g_B.
__global__ void __launch_bounds__(256) k_rowfft(const float* __restrict__ in) {
    __shared__ u64 s[4][S_SZ];
    __shared__ u64 tw[TW_SZ];
    int T = threadIdx.x, f = T >> 6, L = T & 63;
    tw[T + (T >> 4)] = g_tw[T];         // PT(T)
    int bx  = blockIdx.x;               // img*128 + rg
    int img = bx >> 7;
    int rg  = bx & 127;
    int ya  = 4*rg + f;
    __syncthreads();                    // tw ready

    const float* ra = in + ((size_t)img * N + ya) * N;
    const float* rb = ra + (size_t)512 * N;
    // relabeled: this thread runs butterfly group rev4_6(L) -> contiguous loads
    u64 x[16];
    #pragma unroll
    for (int j = 0; j < 16; ++j) {
        int gi = L + 64*((j >> 2) & 3) + 256*(j & 3);
        x[j] = pk(ra[gi], rb[gi]);
    }
    fft_ph1(x, s[f], rev4_6(L));
    __syncthreads();
    fft_ph2(s[f], tw, L);
    __syncthreads();
    fft_ph3(s[f], tw, L, x);
    {   // store naturally-ordered results (same addresses ph3 read: no sync needed)
        int base = 4*L + (L >> 2);
        #pragma unroll
        for (int k = 0; k < 4; ++k)
            #pragma unroll
            for (int q = 0; q < 4; ++q)
                s[f][base + k + 273*q] = x[k + 4*q];
    }
    __syncthreads();                    // all 4 FFTs resident

    // transposed Hermitian unpack: keep kx = 0..512
    int ybase = 4 * rg;
    for (int e = T; e < W; e += 256) {
        int em = (N - e) & (N - 1);
        u64 va[4], vb[4];
        #pragma unroll
        for (int g = 0; g < 4; ++g) {
            float zx, zy, mxx, mxy;
            upk(s[g][P(e)],  zx, zy);
            upk(s[g][P(em)], mxx, mxy);
            va[g] = pk(0.5f*(zx + mxx), 0.5f*(zy - mxy));
            vb[g] = pk(0.5f*(zy + mxy), 0.5f*(mxx - zx));
        }
        u64* pa = g_B + ((size_t)img * WB + e) * N + ybase;
        u64* pb = pa + 512;
        *reinterpret_cast<ulonglong2*>(pa)     = make_ulonglong2(va[0], va[1]);
        *reinterpret_cast<ulonglong2*>(pa + 2) = make_ulonglong2(va[2], va[3]);
        *reinterpret_cast<ulonglong2*>(pb)     = make_ulonglong2(vb[0], vb[1]);
        *reinterpret_cast<ulonglong2*>(pb + 2) = make_ulonglong2(vb[2], vb[3]);
    }
}

// One FFT = one kept column kx. 2 columns per 128-thread block.
// m aliases the exchange buffer (results live in registers after ph3).
__global__ void __launch_bounds__(128) k_colfft(void) {
    __shared__ u64 s[2][S_SZ];
    __shared__ u64 tw[TW_SZ];
    __shared__ float red[8];            // 4 warps: min[0..3], max[4..7]
    int T = threadIdx.x, f = T >> 6, L = T & 63;
    #pragma unroll
    for (int j = T; j < 256; j += 128) tw[j + (j >> 4)] = g_tw[j];
    int bx  = blockIdx.x;               // img*257 + cg
    int img = bx / 257;
    int cg  = bx - img * 257;
    int kx  = 2*cg + f;                 // 0..513 (513 is padding)
    bool valid = (kx < W);
    __syncthreads();                    // tw ready

    const u64* cp = g_B + ((size_t)img * WB + kx) * N;
    // relabeled: contiguous 256B/warp loads
    u64 x[16];
    #pragma unroll
    for (int j = 0; j < 16; ++j)
        x[j] = cp[L + 64*((j >> 2) & 3) + 256*(j & 3)];
    fft_ph1(x, s[f], rev4_6(L));
    __syncthreads();
    fft_ph2(s[f], tw, L);
    __syncthreads();
    fft_ph3(s[f], tw, L, x);
    __syncthreads();                    // all ph3 reads of s done: safe to alias

    // log-magnitude straight from registers; fftshift along ky.
    // m overlays s[f] (4096B of 8736B available).
    float* m = reinterpret_cast<float*>(s[f]);
    float mn = 3.4e38f, mx = 0.0f;
    int mbase = 4*L;
    #pragma unroll
    for (int k = 0; k < 4; ++k)
        #pragma unroll
        for (int q = 0; q < 4; ++q) {
            int cshift = (256*q + 512) & (N - 1);   // literal per q: 512,768,0,256
            float vx, vy; upk(x[k + 4*q], vx, vy);
            float mag = log1pf(sqrtf(vx*vx + vy*vy));
            m[mbase + k + cshift] = mag;
            mn = fminf(mn, mag); mx = fmaxf(mx, mag);
        }
    #pragma unroll
    for (int o = 16; o; o >>= 1) {
        mn = fminf(mn, __shfl_xor_sync(0xffffffffu, mn, o));
        mx = fmaxf(mx, __shfl_xor_sync(0xffffffffu, mx, o));
    }
    int wid = T >> 5;
    if ((T & 31) == 0) { red[wid] = mn; red[4 + wid] = mx; }
    __syncthreads();                    // red + m[] ready
    if (L == 0 && valid) {
        float a  = fminf(red[2*f], red[2*f + 1]);
        float c2 = fmaxf(red[4 + 2*f], red[4 + 2*f + 1]);
        int b = img / 3;
        atomicMin(&g_mn[b], __float_as_uint(a));
        atomicMax(&g_mx[b], __float_as_uint(c2));
    }

    // antialiased triangle resize along kys (ramp weights), column + mirror
    if (valid) {
        int kxs1 = (kx + 512) & (N - 1);
        int kxs2 = 512 - kx;
        float* gt1 = g_T + ((size_t)img * N + kxs1) * OUT_HW;
        float* gt2 = g_T + ((size_t)img * N + kxs2) * OUT_HW;
        for (int oy = L; oy < OUT_HW; oy += 64) {
            float sf = ((float)oy + 0.5f) * (1024.0f/224.0f) - 0.5f;
            int i0 = max(0, (int)ceilf(sf - KRAD));
            int i1 = min(N - 1, (int)floorf(sf + KRAD));
            int ip = (int)floorf(sf);
            float acc1 = 0.0f, acc2 = 0.0f, sw = 0.0f;
            float w = 1.0f - (sf - (float)i0) * KSCL;
            int i = i0;
            for (; i <= ip; ++i) {
                acc1 += w * m[i];
                acc2 += w * m[(N - i) & (N - 1)];
                sw += w; w += KSCL;
            }
            w = 1.0f - ((float)i - sf) * KSCL;
            for (; i <= i1; ++i) {
                acc1 += w * m[i];
                acc2 += w * m[(N - i) & (N - 1)];
                sw += w; w -= KSCL;
            }
            float inv = 1.0f / sw;
            gt1[oy] = acc1 * inv;
            gt2[oy] = acc2 * inv;
        }
    }
}

// kx-resize + normalization. Block = (img, 8 consecutive ox); thread = oy.
// Loads keep the proven coalesced pattern (consecutive oy per tap); the 8
// overlapping tap windows reuse through L1 within the block. Results stage
// through a padded shared tile so stores are 32B-contiguous chunks.
__global__ void __launch_bounds__(224) k_resize2(float* __restrict__ out) {
    __shared__ float ts[224][9];        // [oy][ox8], pad 9 to dodge conflicts
    int bx  = blockIdx.x;               // img*28 + og
    int img = bx / 28;
    int og  = bx - img * 28;
    int ox0 = og * 8;
    int T   = threadIdx.x;              // = oy

    const float* base = g_T + (size_t)img * N * OUT_HW + T;
    int b = img / 3;
    float mn  = __uint_as_float(g_mn[b]);
    float mxv = __uint_as_float(g_mx[b]);
    float nrm = 1.0f / (mxv - mn + 1e-8f);

    #pragma unroll
    for (int k = 0; k < 8; ++k) {
        int ox = ox0 + k;
        float sf = ((float)ox + 0.5f) * (1024.0f/224.0f) - 0.5f;
        int i0 = max(0, (int)ceilf(sf - KRAD));
        int i1 = min(N - 1, (int)floorf(sf + KRAD));
        int ip = (int)floorf(sf);
        float acc = 0.0f, sw = 0.0f;
        float w = 1.0f - (sf - (float)i0) * KSCL;
        int i = i0;
        for (; i <= ip; ++i) { acc += w * base[(size_t)i * OUT_HW]; sw += w; w += KSCL; }
        w = 1.0f - ((float)i - sf) * KSCL;
        for (; i <= i1; ++i) { acc += w * base[(size_t)i * OUT_HW]; sw += w; w -= KSCL; }
        ts[T][k] = (acc / sw - mn) * nrm;
    }
    __syncthreads();

    // cooperative coalesced store of the [224 oy][8 ox] tile
    float* op = out + (size_t)img * OUT_HW * OUT_HW + ox0;
    for (int e = T; e < 224 * 8; e += 224) {
        int row = e >> 3, col = e & 7;
        op[(size_t)row * OUT_HW + col] = ts[row][col];
    }
}

extern "C" void kernel_launch(void* const* d_in, const int* in_sizes, int n_in,
                              void* d_out, int out_size) {
    (void)in_sizes; (void)n_in; (void)out_size;
    const float* in = (const float*)d_in[0];
    float* out = (float*)d_out;

    k_init<<<1, 256>>>();
    k_rowfft<<<NIMG * 128, 256>>>(in);
    k_colfft<<<NIMG * 257, 128>>>();
    k_resize2<<<NIMG * 28, 224>>>(out);
}

// round 15
// speedup vs baseline: 1.0975x; 1.0240x over previous
#include <cuda_runtime.h>
#include <math.h>

#define NIMG 48            // B*C = 16*3
#define NBATCH 16
#define N 1024
#define OUT_HW 224
#define W 513              // kept kx columns (Hermitian half)
#define WB 514             // padded kx rows in g_B
#define KRAD (1024.0f/224.0f)
#define KSCL (224.0f/1024.0f)

// padded shared indexing (generic form, used only in the Hermitian unpack)
#define P(i)  ((i) + ((i) >> 4) + ((i) >> 8))
#define S_SZ  1092
#define TW_SZ 272

typedef unsigned long long u64;

// scratch (static device arrays; no allocation allowed)
__device__ u64   g_B[(size_t)NIMG * WB * N];        // column-major spectra [img][kx][y]
__device__ float g_T[(size_t)NIMG * N * OUT_HW];    // ky-resized [img][kxs][oy]
__device__ u64   g_tw[256];
__device__ unsigned int g_mn[NBATCH];
__device__ unsigned int g_mx[NBATCH];

// ---------- packed f32x2 complex primitives ----------
__device__ __forceinline__ u64 pk(float x, float y) {
    u64 r; asm("mov.b64 %0, {%1,%2};" : "=l"(r) : "f"(x), "f"(y)); return r;
}
__device__ __forceinline__ void upk(u64 a, float& x, float& y) {
    asm("mov.b64 {%0,%1}, %2;" : "=f"(x), "=f"(y) : "l"(a));
}
__device__ __forceinline__ u64 vadd(u64 a, u64 b) {
    u64 r; asm("add.rn.f32x2 %0, %1, %2;" : "=l"(r) : "l"(a), "l"(b)); return r;
}
__device__ __forceinline__ u64 vfma(u64 a, u64 b, u64 c) {
    u64 r; asm("fma.rn.f32x2 %0, %1, %2, %3;" : "=l"(r) : "l"(a), "l"(b), "l"(c)); return r;
}
#define K_NEG1 0xBF800000BF800000ULL   // (-1,-1)
#define K_PM1  0xBF8000003F800000ULL   // lo:+1, hi:-1
#define K_MP1  0x3F800000BF800000ULL   // lo:-1, hi:+1
__device__ __forceinline__ u64 vsub(u64 a, u64 b) { return vfma(b, K_NEG1, a); }  // a-b

// scalar complex multiply on packed values
__device__ __forceinline__ u64 cmul(u64 a, u64 b) {
    float ax, ay, bx, by; upk(a, ax, ay); upk(b, bx, by);
    return pk(ax*bx - ay*by, ax*by + ay*bx);
}
__device__ __forceinline__ u64 cmulc(u64 a, float bx, float by) {
    float ax, ay; upk(a, ax, ay);
    return pk(ax*bx - ay*by, ax*by + ay*bx);
}

// packed radix-4 DIT butterfly, in place
__device__ __forceinline__ void bfly4p(u64& x0, u64& x1, u64& x2, u64& x3) {
    u64 u0 = vadd(x0, x2);
    u64 u1 = vsub(x0, x2);
    u64 u2 = vadd(x1, x3);
    u64 u3 = vsub(x1, x3);
    x0 = vadd(u0, u2);
    x2 = vsub(u0, u2);
    float ux, uy; upk(u3, ux, uy);
    u64 sw = pk(uy, ux);
    x1 = vfma(sw, K_PM1, u1);   // (u1.x + u3.y, u1.y - u3.x)
    x3 = vfma(sw, K_MP1, u1);   // (u1.x - u3.y, u1.y + u3.x)
}

// butterfly with precomputed twiddle powers
__device__ __forceinline__ void stage3(u64& a0, u64& a1, u64& a2, u64& a3,
                                       u64 w1, u64 w2, u64 w3) {
    a1 = cmul(a1, w1); a2 = cmul(a2, w2); a3 = cmul(a3, w3);
    bfly4p(a0, a1, a2, a3);
}

// base-4 digit reversal of a 6-bit index (64 = 4^3), self-inverse
__device__ __forceinline__ int rev4_6(int b) {
    return ((b & 3) << 4) | (b & 12) | (b >> 4);
}

// ---------- FFT phases (1024 pts, 64 threads/FFT, 16 pts/thread) ----------
// phase 1: stages 0+1 in registers, store to shared at affine offsets.
// Caller passes b = rev4_6(L) so the global loads stay contiguous in L.
__device__ __forceinline__ void fft_ph1(u64 x[16], u64* s, int b) {
    #pragma unroll
    for (int k = 0; k < 4; ++k) bfly4p(x[4*k], x[4*k+1], x[4*k+2], x[4*k+3]);
    bfly4p(x[0], x[4], x[8], x[12]);                       // pos=0: no twiddle
    x[5]  = cmulc(x[5],   0.92387953f, -0.38268343f);      // pos=1: w, w^2, w^3
    x[9]  = cmulc(x[9],   0.70710678f, -0.70710678f);
    x[13] = cmulc(x[13],  0.38268343f, -0.92387953f);
    bfly4p(x[1], x[5], x[9], x[13]);
    x[6]  = cmulc(x[6],   0.70710678f, -0.70710678f);      // pos=2
    x[10] = cmulc(x[10],  0.0f,        -1.0f);
    x[14] = cmulc(x[14], -0.70710678f, -0.70710678f);
    bfly4p(x[2], x[6], x[10], x[14]);
    x[7]  = cmulc(x[7],   0.38268343f, -0.92387953f);      // pos=3
    x[11] = cmulc(x[11], -0.70710678f, -0.70710678f);
    x[15] = cmulc(x[15], -0.92387953f,  0.38268343f);
    bfly4p(x[3], x[7], x[11], x[15]);
    int b17 = 17*b + (b >> 4);          // == P(16b + j) - j
    #pragma unroll
    for (int j = 0; j < 16; ++j) s[b17 + j] = x[j];
}

// phase 2: stages 2+3 in registers. P(c+16q2+64q3+256hi) = (c+273hi)+17q2+68q3
__device__ __forceinline__ void fft_ph2(u64* s, const u64* tw, int L) {
    int c = L & 15, hi = L >> 4;
    int base = c + 273*hi;
    u64 x[16];
    #pragma unroll
    for (int q3 = 0; q3 < 4; ++q3)
        #pragma unroll
        for (int q2 = 0; q2 < 4; ++q2)
            x[q2 + 4*q3] = s[base + 17*q2 + 68*q3];
    u64 w1 = tw[17*c];                  // PT(16c) = 17c
    u64 w2 = cmul(w1, w1);
    u64 w3 = cmul(w2, w1);
    #pragma unroll
    for (int q3 = 0; q3 < 4; ++q3)
        stage3(x[4*q3], x[4*q3+1], x[4*q3+2], x[4*q3+3], w1, w2, w3);
    u64 v1 = tw[4*c + (c >> 2)];        // PT(4c)
    const float wc[4] = {1.0f, 0.92387953f, 0.70710678f, 0.38268343f};
    const float ws[4] = {0.0f, -0.38268343f, -0.70710678f, -0.92387953f};
    #pragma unroll
    for (int q2 = 0; q2 < 4; ++q2) {
        u64 w = (q2 == 0) ? v1 : cmulc(v1, wc[q2], ws[q2]);
        u64 ww2 = cmul(w, w);
        u64 ww3 = cmul(ww2, w);
        stage3(x[q2], x[q2+4], x[q2+8], x[q2+12], w, ww2, ww3);
    }
    #pragma unroll
    for (int q3 = 0; q3 < 4; ++q3)
        #pragma unroll
        for (int q2 = 0; q2 < 4; ++q2)
            s[base + 17*q2 + 68*q3] = x[q2 + 4*q3];
}

// phase 3: stage 4. P(4L+k+256q) = (4L+(L>>2)) + k + 273q; tw index = base+k.
// Result: x[k+4q] = DFT[4L+k+256q] (natural order).
__device__ __forceinline__ void fft_ph3(u64* s, const u64* tw, int L, u64 x[16]) {
    int base = 4*L + (L >> 2);
    #pragma unroll
    for (int k = 0; k < 4; ++k) {
        u64 w1 = tw[base + k];
        u64 w2 = cmul(w1, w1);
        u64 w3 = cmul(w2, w1);
        u64 a0 = s[base + k];
        u64 a1 = s[base + k + 273];
        u64 a2 = s[base + k + 546];
        u64 a3 = s[base + k + 819];
        a1 = cmul(a1, w1); a2 = cmul(a2, w2); a3 = cmul(a3, w3);
        bfly4p(a0, a1, a2, a3);
        x[k] = a0; x[k+4] = a1; x[k+8] = a2; x[k+12] = a3;
    }
}

__global__ void k_init(void) {
    int t = threadIdx.x;
    if (t < NBATCH) { g_mn[t] = 0x7f800000u; g_mx[t] = 0u; }
    float sn, cs;
    sincosf(-6.283185307179586f * (float)t / 1024.0f, &sn, &cs);
    g_tw[t] = pk(cs, sn);
}

// 4 FFTs per 256-thread block; each FFT = two real rows (ya, ya+512) packed.
// Hermitian unpack writes transposed 32B chunks directly into g_B.
__global__ void __launch_bounds__(256) k_rowfft(const float* __restrict__ in) {
    __shared__ u64 s[4][S_SZ];
    __shared__ u64 tw[TW_SZ];
    int T = threadIdx.x, f = T >> 6, L = T & 63;
    tw[T + (T >> 4)] = g_tw[T];         // PT(T)
    int bx  = blockIdx.x;               // img*128 + rg
    int img = bx >> 7;
    int rg  = bx & 127;
    int ya  = 4*rg + f;
    __syncthreads();                    // tw ready

    const float* ra = in + ((size_t)img * N + ya) * N;
    const float* rb = ra + (size_t)512 * N;
    // relabeled: this thread runs butterfly group rev4_6(L) -> contiguous loads
    u64 x[16];
    #pragma unroll
    for (int j = 0; j < 16; ++j) {
        int gi = L + 64*((j >> 2) & 3) + 256*(j & 3);
        x[j] = pk(ra[gi], rb[gi]);
    }
    fft_ph1(x, s[f], rev4_6(L));
    __syncthreads();
    fft_ph2(s[f], tw, L);
    __syncthreads();
    fft_ph3(s[f], tw, L, x);
    {   // store naturally-ordered results (same addresses ph3 read: no sync needed)
        int base = 4*L + (L >> 2);
        #pragma unroll
        for (int k = 0; k < 4; ++k)
            #pragma unroll
            for (int q = 0; q < 4; ++q)
                s[f][base + k + 273*q] = x[k + 4*q];
    }
    __syncthreads();                    // all 4 FFTs resident

    // transposed Hermitian unpack: keep kx = 0..512
    int ybase = 4 * rg;
    for (int e = T; e < W; e += 256) {
        int em = (N - e) & (N - 1);
        u64 va[4], vb[4];
        #pragma unroll
        for (int g = 0; g < 4; ++g) {
            float zx, zy, mxx, mxy;
            upk(s[g][P(e)],  zx, zy);
            upk(s[g][P(em)], mxx, mxy);
            va[g] = pk(0.5f*(zx + mxx), 0.5f*(zy - mxy));
            vb[g] = pk(0.5f*(zy + mxy), 0.5f*(mxx - zx));
        }
        u64* pa = g_B + ((size_t)img * WB + e) * N + ybase;
        u64* pb = pa + 512;
        *reinterpret_cast<ulonglong2*>(pa)     = make_ulonglong2(va[0], va[1]);
        *reinterpret_cast<ulonglong2*>(pa + 2) = make_ulonglong2(va[2], va[3]);
        *reinterpret_cast<ulonglong2*>(pb)     = make_ulonglong2(vb[0], vb[1]);
        *reinterpret_cast<ulonglong2*>(pb + 2) = make_ulonglong2(vb[2], vb[3]);
    }
}

// One FFT = one kept column kx. 2 columns per 128-thread block.
// m aliases the exchange buffer (results live in registers after ph3).
__global__ void __launch_bounds__(128) k_colfft(void) {
    __shared__ u64 s[2][S_SZ];
    __shared__ u64 tw[TW_SZ];
    __shared__ float red[8];            // 4 warps: min[0..3], max[4..7]
    int T = threadIdx.x, f = T >> 6, L = T & 63;
    #pragma unroll
    for (int j = T; j < 256; j += 128) tw[j + (j >> 4)] = g_tw[j];
    int bx  = blockIdx.x;               // img*257 + cg
    int img = bx / 257;
    int cg  = bx - img * 257;
    int kx  = 2*cg + f;                 // 0..513 (513 is padding)
    bool valid = (kx < W);
    __syncthreads();                    // tw ready

    const u64* cp = g_B + ((size_t)img * WB + kx) * N;
    // relabeled: contiguous 256B/warp loads
    u64 x[16];
    #pragma unroll
    for (int j = 0; j < 16; ++j)
        x[j] = cp[L + 64*((j >> 2) & 3) + 256*(j & 3)];
    fft_ph1(x, s[f], rev4_6(L));
    __syncthreads();
    fft_ph2(s[f], tw, L);
    __syncthreads();
    fft_ph3(s[f], tw, L, x);
    __syncthreads();                    // all ph3 reads of s done: safe to alias

    // log-magnitude straight from registers; fftshift along ky.
    // m overlays s[f] (4096B of 8736B available).
    float* m = reinterpret_cast<float*>(s[f]);
    float mn = 3.4e38f, mx = 0.0f;
    int mbase = 4*L;
    #pragma unroll
    for (int k = 0; k < 4; ++k)
        #pragma unroll
        for (int q = 0; q < 4; ++q) {
            int cshift = (256*q + 512) & (N - 1);   // literal per q: 512,768,0,256
            float vx, vy; upk(x[k + 4*q], vx, vy);
            float mag = log1pf(sqrtf(vx*vx + vy*vy));
            m[mbase + k + cshift] = mag;
            mn = fminf(mn, mag); mx = fmaxf(mx, mag);
        }
    #pragma unroll
    for (int o = 16; o; o >>= 1) {
        mn = fminf(mn, __shfl_xor_sync(0xffffffffu, mn, o));
        mx = fmaxf(mx, __shfl_xor_sync(0xffffffffu, mx, o));
    }
    int wid = T >> 5;
    if ((T & 31) == 0) { red[wid] = mn; red[4 + wid] = mx; }
    __syncthreads();                    // red + m[] ready
    if (L == 0 && valid) {
        float a  = fminf(red[2*f], red[2*f + 1]);
        float c2 = fmaxf(red[4 + 2*f], red[4 + 2*f + 1]);
        int b = img / 3;
        atomicMin(&g_mn[b], __float_as_uint(a));
        atomicMax(&g_mx[b], __float_as_uint(c2));
    }

    // antialiased triangle resize along kys: fixed 10-tap unrolled window,
    // weights precomputed (zero outside [0,1023] -> same renorm as before),
    // even/odd accumulator pairs for ILP. Column + Hermitian mirror.
    if (valid) {
        int kxs1 = (kx + 512) & (N - 1);
        int kxs2 = 512 - kx;
        float* gt1 = g_T + ((size_t)img * N + kxs1) * OUT_HW;
        float* gt2 = g_T + ((size_t)img * N + kxs2) * OUT_HW;
        for (int oy = L; oy < OUT_HW; oy += 64) {
            float sf = ((float)oy + 0.5f) * (1024.0f/224.0f) - 0.5f;
            int iL = (int)ceilf(sf - KRAD);
            float wt[10];
            float sw = 0.0f;
            #pragma unroll
            for (int j = 0; j < 10; ++j) {
                int i = iL + j;
                float wv = fmaxf(0.0f, 1.0f - fabsf(sf - (float)i) * KSCL);
                wv = ((unsigned)i <= 1023u) ? wv : 0.0f;
                wt[j] = wv; sw += wv;
            }
            float a1 = 0.f, b1 = 0.f, a2 = 0.f, b2 = 0.f;
            #pragma unroll
            for (int j = 0; j < 10; j += 2) {
                int ia = (iL + j) & 1023;
                int ib = (iL + j + 1) & 1023;
                a1 += wt[j]   * m[ia];
                b1 += wt[j+1] * m[ib];
                a2 += wt[j]   * m[(1024 - (iL + j)) & 1023];
                b2 += wt[j+1] * m[(1024 - (iL + j + 1)) & 1023];
            }
            float inv = 1.0f / sw;
            gt1[oy] = (a1 + b1) * inv;
            gt2[oy] = (a2 + b2) * inv;
        }
    }
}

// kx-resize + normalization. Block = (img, 8 consecutive ox); thread = oy.
// Tap weights computed ONCE per block into shared (broadcast reads); inner
// loop is pure FMA + L1-hit loads, fully unrolled (fixed 10 taps). Results
// stage through a padded shared tile so stores are 32B-contiguous chunks.
__global__ void __launch_bounds__(224) k_resize2(float* __restrict__ out) {
    __shared__ float ts[224][9];        // [oy][ox8], pad 9 to dodge conflicts
    __shared__ float ws[8][10];
    __shared__ float winv[8];
    __shared__ int   wil[8];
    int bx  = blockIdx.x;               // img*28 + og
    int img = bx / 28;
    int og  = bx - img * 28;
    int ox0 = og * 8;
    int T   = threadIdx.x;              // = oy

    if (T < 8) {
        int ox = ox0 + T;
        float sf = ((float)ox + 0.5f) * (1024.0f/224.0f) - 0.5f;
        int iL = (int)ceilf(sf - KRAD);
        wil[T] = iL;
        float sw = 0.0f;
        #pragma unroll
        for (int j = 0; j < 10; ++j) {
            int i = iL + j;
            float wv = fmaxf(0.0f, 1.0f - fabsf(sf - (float)i) * KSCL);
            wv = ((unsigned)i <= 1023u) ? wv : 0.0f;
            ws[T][j] = wv; sw += wv;
        }
        winv[T] = 1.0f / sw;
    }
    int b = img / 3;
    float mn  = __uint_as_float(g_mn[b]);
    float nrm = 1.0f / (__uint_as_float(g_mx[b]) - mn + 1e-8f);
    __syncthreads();

    const float* base = g_T + (size_t)img * N * OUT_HW + T;
    #pragma unroll
    for (int k = 0; k < 8; ++k) {
        int iL = wil[k];
        float a = 0.f, c = 0.f;
        #pragma unroll
        for (int j = 0; j < 10; j += 2) {
            a += ws[k][j]   * base[(size_t)((iL + j)     & 1023) * OUT_HW];
            c += ws[k][j+1] * base[(size_t)((iL + j + 1) & 1023) * OUT_HW];
        }
        ts[T][k] = ((a + c) * winv[k] - mn) * nrm;
    }
    __syncthreads();

    // cooperative coalesced store of the [224 oy][8 ox] tile
    float* op = out + (size_t)img * OUT_HW * OUT_HW + ox0;
    for (int e = T; e < 224 * 8; e += 224) {
        int row = e >> 3, col = e & 7;
        op[(size_t)row * OUT_HW + col] = ts[row][col];
    }
}

extern "C" void kernel_launch(void* const* d_in, const int* in_sizes, int n_in,
                              void* d_out, int out_size) {
    (void)in_sizes; (void)n_in; (void)out_size;
    const float* in = (const float*)d_in[0];
    float* out = (float*)d_out;

    k_init<<<1, 256>>>();
    k_rowfft<<<NIMG * 128, 256>>>(in);
    k_colfft<<<NIMG * 257, 128>>>();
    k_resize2<<<NIMG * 28, 224>>>(out);
}